// round 16
// baseline (speedup 1.0000x reference)
#include <cuda_runtime.h>
#include <math.h>
#include <stdint.h>

#define SEQ 2048
#define HID 1024
#define NH 16
#define HD 64
#define CHUNK 64
#define NCHUNK (SEQ / CHUNK)

// ---------------- scratch ----------------
__device__ float g_q[SEQ * HID];
__device__ float g_k[SEQ * HID];
__device__ float g_v[SEQ * HID];
__device__ float g_att[SEQ * HID];            // pre-rounded to tf32
__device__ float g_S[NH * NCHUNK * HD * HD];  // stored TRANSPOSED: S_store[e][d] = S[d][e]
__device__ float g_Z[NH * NCHUNK * HD];
__device__ float g_xr[SEQ * HID];
__device__ float g_wqr[HID * HID];
__device__ float g_wkr[HID * HID];
__device__ float g_wvr[HID * HID];
__device__ float g_wor[HID * HID];

__device__ __forceinline__ uint32_t f2tf32(float f) {
    uint32_t u;
    asm("cvt.rna.tf32.f32 %0, %1;" : "=r"(u) : "f"(f));
    return u;
}
__device__ __forceinline__ float rndtf32(float f) { return __uint_as_float(f2tf32(f)); }
__device__ __forceinline__ uint32_t smem_u32(const void* p) {
    uint32_t a;
    asm("{ .reg .u64 t; cvta.to.shared.u64 t, %1; cvt.u32.u64 %0, t; }" : "=r"(a) : "l"(p));
    return a;
}
__device__ __forceinline__ void split32(float f, uint32_t& hi, uint32_t& lo) {
    float fh = rndtf32(f);
    hi = __float_as_uint(fh);
    lo = f2tf32(f - fh);
}

#define MMA_TF32(c0,c1,c2,c3,a0,a1,a2,a3,b0,b1) \
    asm volatile("mma.sync.aligned.m16n8k8.row.col.f32.tf32.tf32.f32 " \
                 "{%0,%1,%2,%3}, {%4,%5,%6,%7}, {%8,%9}, {%0,%1,%2,%3};" \
                 : "+f"(c0), "+f"(c1), "+f"(c2), "+f"(c3) \
                 : "r"(a0), "r"(a1), "r"(a2), "r"(a3), "r"(b0), "r"(b1))

#define MMA3(C, ah, al, bh, bl) do { \
    MMA_TF32(C[0],C[1],C[2],C[3], ah[0],ah[1],ah[2],ah[3], bh[0],bh[1]); \
    MMA_TF32(C[0],C[1],C[2],C[3], ah[0],ah[1],ah[2],ah[3], bl[0],bl[1]); \
    MMA_TF32(C[0],C[1],C[2],C[3], al[0],al[1],al[2],al[3], bh[0],bh[1]); \
} while (0)

// ---------------- fused pre-round pass ----------------
#define X4 (SEQ * HID / 4)
#define W4 (HID * HID / 4)
__global__ __launch_bounds__(256) void round_all_kernel(
    const float* __restrict__ x, const float* __restrict__ Wq,
    const float* __restrict__ Wk, const float* __restrict__ Wv,
    const float* __restrict__ Wo)
{
    int i = blockIdx.x * 256 + threadIdx.x;
    const float4* src;
    float4* dst;
    int off;
    if (i < X4) { src = (const float4*)x; dst = (float4*)g_xr; off = i; }
    else {
        int j = i - X4;
        int seg = j >> 18;
        off = j & (W4 - 1);
        src = (const float4*)((seg == 0) ? Wq : (seg == 1) ? Wk : (seg == 2) ? Wv : Wo);
        dst = (float4*)((seg == 0) ? g_wqr : (seg == 1) ? g_wkr : (seg == 2) ? g_wvr : g_wor);
    }
    float4 v = src[off];
    v.x = rndtf32(v.x); v.y = rndtf32(v.y); v.z = rndtf32(v.z); v.w = rndtf32(v.w);
    dst[off] = v;
}

// ================= pipelined tf32 mma GEMM (R11 schedule: both barriers) =================
#define GBK 32
#define GSTRIDE 36
#define NSTAGE (HID / GBK)
#define NBUF 3
#define TILE_FLOATS (128 * GSTRIDE)
#define STAGE_FLOATS (2 * TILE_FLOATS)
#define GEMM_SMEM (NBUF * STAGE_FLOATS * 4)

__device__ __forceinline__ void cpasync16(uint32_t saddr, const float* gaddr) {
    asm volatile("cp.async.cg.shared.global [%0], [%1], 16;" :: "r"(saddr), "l"(gaddr));
}

__device__ __forceinline__ void gemm_body(const float* __restrict__ A,
                                          const float* __restrict__ B,
                                          float* __restrict__ C, int act,
                                          int m0, int n0, char* smem)
{
    const uint32_t sbase = smem_u32(smem);
    const int tid = threadIdx.x;
    const int w = tid >> 5;
    const int lane = tid & 31;
    const int g = lane >> 2;
    const int l4 = lane & 3;
    const int wm = (w >> 2) * 64;
    const int wn = (w & 3) * 32;

    float c[4][4][4];
#pragma unroll
    for (int mi = 0; mi < 4; mi++)
#pragma unroll
        for (int ni = 0; ni < 4; ni++)
#pragma unroll
            for (int q = 0; q < 4; q++) c[mi][ni][q] = 0.f;

    auto prefetch = [&](int s) {
        const int b = s % NBUF;
        const uint32_t ab = sbase + (uint32_t)(b * STAGE_FLOATS) * 4;
        const uint32_t bb = ab + TILE_FLOATS * 4;
        const int k0 = s * GBK;
#pragma unroll
        for (int p = 0; p < 4; p++) {
            const int idx = tid + p * 256;
            const int r = idx >> 3, kk = (idx & 7) * 4;
            cpasync16(ab + (r * GSTRIDE + kk) * 4, &A[(size_t)(m0 + r) * HID + k0 + kk]);
            cpasync16(bb + (r * GSTRIDE + kk) * 4, &B[(size_t)(n0 + r) * HID + k0 + kk]);
        }
        asm volatile("cp.async.commit_group;" ::: "memory");
    };

    prefetch(0);
    prefetch(1);

    for (int s = 0; s < NSTAGE; s++) {
        asm volatile("cp.async.wait_group 1;" ::: "memory");
        __syncthreads();
        if (s + 2 < NSTAGE) prefetch(s + 2);

        const int b = s % NBUF;
        const float* As = (const float*)(smem) + b * STAGE_FLOATS;
        const float* Bs = As + TILE_FLOATS;

#pragma unroll
        for (int kk = 0; kk < GBK; kk += 8) {
            uint32_t a[4][4], bq[4][2];
#pragma unroll
            for (int mi = 0; mi < 4; mi++) {
                const int r = wm + mi * 16 + g;
                a[mi][0] = __float_as_uint(As[r * GSTRIDE + kk + l4]);
                a[mi][1] = __float_as_uint(As[(r + 8) * GSTRIDE + kk + l4]);
                a[mi][2] = __float_as_uint(As[r * GSTRIDE + kk + l4 + 4]);
                a[mi][3] = __float_as_uint(As[(r + 8) * GSTRIDE + kk + l4 + 4]);
            }
#pragma unroll
            for (int ni = 0; ni < 4; ni++) {
                const int r = wn + ni * 8 + g;
                bq[ni][0] = __float_as_uint(Bs[r * GSTRIDE + kk + l4]);
                bq[ni][1] = __float_as_uint(Bs[r * GSTRIDE + kk + l4 + 4]);
            }
#pragma unroll
            for (int mi = 0; mi < 4; mi++)
#pragma unroll
                for (int ni = 0; ni < 4; ni++)
                    MMA_TF32(c[mi][ni][0], c[mi][ni][1], c[mi][ni][2], c[mi][ni][3],
                             a[mi][0], a[mi][1], a[mi][2], a[mi][3],
                             bq[ni][0], bq[ni][1]);
        }
        __syncthreads();   // restored: keeps warps stage-converged (R12/R13 removal regressed)
    }
    asm volatile("cp.async.wait_group 0;" ::: "memory");

#pragma unroll
    for (int mi = 0; mi < 4; mi++) {
#pragma unroll
        for (int ri = 0; ri < 2; ri++) {
            const int m = m0 + wm + mi * 16 + g + ri * 8;
#pragma unroll
            for (int ni = 0; ni < 4; ni++) {
                float y0 = c[mi][ni][ri * 2 + 0];
                float y1 = c[mi][ni][ri * 2 + 1];
                if (act) {
                    y0 = (y0 > 0.f) ? (y0 + 1.f) : expf(y0);
                    y1 = (y1 > 0.f) ? (y1 + 1.f) : expf(y1);
                }
                const int n = n0 + wn + ni * 8 + l4 * 2;
                *(float2*)&C[(size_t)m * HID + n] = make_float2(y0, y1);
            }
        }
    }
}

extern __shared__ char sm_g[];
__global__ __launch_bounds__(256, 2) void gemm_qkv_kernel()
{
    const int z = blockIdx.z;
    const float* W = (z == 0) ? g_wqr : (z == 1) ? g_wkr : g_wvr;
    float* dst = (z == 0) ? g_q : (z == 1) ? g_k : g_v;
    gemm_body(g_xr, W, dst, z != 2, blockIdx.y * 128, blockIdx.x * 128, sm_g);
}
__global__ __launch_bounds__(256, 2) void gemm_out_kernel(float* __restrict__ out)
{
    gemm_body(g_att, g_wor, out, 0, blockIdx.y * 128, blockIdx.x * 128, sm_g);
}

// ================= Pass A: per-chunk S=K^T V (3xTF32, pre-split smem) =================
#define PS 68
#define STATS_SMEM (4 * 64 * PS * 4)   // Kth, Ktl, Vth, Vtl = 69632 B
extern __shared__ uint32_t sm_s[];
__global__ __launch_bounds__(256) void chunk_stats_kernel()
{
    const int c = blockIdx.x;
    const int h = blockIdx.y;
    uint32_t* Kth = sm_s;
    uint32_t* Ktl = Kth + 64 * PS;
    uint32_t* Vth = Ktl + 64 * PS;
    uint32_t* Vtl = Vth + 64 * PS;

    const int tid = threadIdx.x;
    const int t0 = c * CHUNK;

#pragma unroll
    for (int p = 0; p < 4; p++) {
        const int idx = tid + p * 256;
        const int t = idx >> 4;
        const int e4 = (idx & 15) * 4;
        float4 kv = *(const float4*)&g_k[(size_t)(t0 + t) * HID + h * HD + e4];
        float4 vv = *(const float4*)&g_v[(size_t)(t0 + t) * HID + h * HD + e4];
        uint32_t hi, lo;
        split32(kv.x, hi, lo); Kth[(e4 + 0) * PS + t] = hi; Ktl[(e4 + 0) * PS + t] = lo;
        split32(kv.y, hi, lo); Kth[(e4 + 1) * PS + t] = hi; Ktl[(e4 + 1) * PS + t] = lo;
        split32(kv.z, hi, lo); Kth[(e4 + 2) * PS + t] = hi; Ktl[(e4 + 2) * PS + t] = lo;
        split32(kv.w, hi, lo); Kth[(e4 + 3) * PS + t] = hi; Ktl[(e4 + 3) * PS + t] = lo;
        split32(vv.x, hi, lo); Vth[(e4 + 0) * PS + t] = hi; Vtl[(e4 + 0) * PS + t] = lo;
        split32(vv.y, hi, lo); Vth[(e4 + 1) * PS + t] = hi; Vtl[(e4 + 1) * PS + t] = lo;
        split32(vv.z, hi, lo); Vth[(e4 + 2) * PS + t] = hi; Vtl[(e4 + 2) * PS + t] = lo;
        split32(vv.w, hi, lo); Vth[(e4 + 3) * PS + t] = hi; Vtl[(e4 + 3) * PS + t] = lo;
    }
    __syncthreads();

    if (tid < HD) {
        float z = 0.f;
        for (int t = 0; t < CHUNK; t++)
            z += __uint_as_float(Kth[tid * PS + t]) + __uint_as_float(Ktl[tid * PS + t]);
        g_Z[(size_t)(h * NCHUNK + c) * HD + tid] = z;
    }

    const int w = tid >> 5, lane = tid & 31;
    const int g = lane >> 2, l4 = lane & 3;
    const int wm = (w >> 1) * 16;
    const int wn = (w & 1) * 32;

    float cc[4][4];
#pragma unroll
    for (int ni = 0; ni < 4; ni++)
#pragma unroll
        for (int q = 0; q < 4; q++) cc[ni][q] = 0.f;

#pragma unroll
    for (int ks = 0; ks < 8; ks++) {
        const int k0 = ks * 8;
        uint32_t ah[4], al[4];
        ah[0] = Vth[(wm + g) * PS + k0 + l4];         al[0] = Vtl[(wm + g) * PS + k0 + l4];
        ah[1] = Vth[(wm + g + 8) * PS + k0 + l4];     al[1] = Vtl[(wm + g + 8) * PS + k0 + l4];
        ah[2] = Vth[(wm + g) * PS + k0 + l4 + 4];     al[2] = Vtl[(wm + g) * PS + k0 + l4 + 4];
        ah[3] = Vth[(wm + g + 8) * PS + k0 + l4 + 4]; al[3] = Vtl[(wm + g + 8) * PS + k0 + l4 + 4];
#pragma unroll
        for (int ni = 0; ni < 4; ni++) {
            const int d = wn + ni * 8 + g;
            uint32_t bh[2], bl[2];
            bh[0] = Kth[d * PS + k0 + l4];     bl[0] = Ktl[d * PS + k0 + l4];
            bh[1] = Kth[d * PS + k0 + l4 + 4]; bl[1] = Ktl[d * PS + k0 + l4 + 4];
            MMA3(cc[ni], ah, al, bh, bl);
        }
    }

    float* Sout = g_S + (size_t)(h * NCHUNK + c) * HD * HD;
#pragma unroll
    for (int ni = 0; ni < 4; ni++) {
        const int d = wn + ni * 8 + l4 * 2;
        *(float2*)&Sout[(wm + g) * HD + d]     = make_float2(cc[ni][0], cc[ni][1]);
        *(float2*)&Sout[(wm + g + 8) * HD + d] = make_float2(cc[ni][2], cc[ni][3]);
    }
}

// ---------------- Pass B: PARALLEL exclusive scan, register-batched (MLP=16) ----------------
#define SCAN_S_BLOCKS (NH * HD * HD / 256)   // 256
__global__ __launch_bounds__(256) void chunk_scan_kernel()
{
    const int bid = blockIdx.x;
    const int tid = threadIdx.x;
    if (bid < SCAN_S_BLOCKS) {
        const int gidx = bid * 256 + tid;
        const int h = gidx >> 12;
        const int e = gidx & 4095;
        float* p = g_S + (size_t)h * NCHUNK * HD * HD + e;
        float acc = 0.f;
#pragma unroll
        for (int b = 0; b < 2; b++) {
            float v[16];
#pragma unroll
            for (int i = 0; i < 16; i++)
                v[i] = p[(size_t)(b * 16 + i) * (HD * HD)];
#pragma unroll
            for (int i = 0; i < 16; i++) {
                p[(size_t)(b * 16 + i) * (HD * HD)] = acc;
                acc += v[i];
            }
        }
    } else {
        const int j = (bid - SCAN_S_BLOCKS) * 256 + tid;
        const int h = j >> 6;
        const int d = j & 63;
        float* p = g_Z + (size_t)h * NCHUNK * HD + d;
        float acc = 0.f;
#pragma unroll
        for (int b = 0; b < 2; b++) {
            float v[16];
#pragma unroll
            for (int i = 0; i < 16; i++)
                v[i] = p[(b * 16 + i) * HD];
#pragma unroll
            for (int i = 0; i < 16; i++) {
                p[(b * 16 + i) * HD] = acc;
                acc += v[i];
            }
        }
    }
}

// ================= Pass C: per-chunk output (3xTF32) =================
extern __shared__ float sm_c[];
__global__ __launch_bounds__(256) void chunk_out_kernel()
{
    const int c = blockIdx.x;
    const int h = blockIdx.y;
    float* Qs  = sm_c;                 // [64][PS] (t,d)
    float* Kb  = Qs + 64 * PS;         // [64][PS] (s,d)
    float* Spt = Kb + 64 * PS;         // [64][PS] S_store[e][d]
    float* Vt  = Spt + 64 * PS;        // [64][PS] Vt[e][s]
    float* Am  = Vt + 64 * PS;         // [64][PS] masked QK^T (t,s)
    __shared__ float zprev[HD];
    __shared__ float rowpart[HD][2];
    __shared__ float dinv[CHUNK];

    const int tid = threadIdx.x;
    const int t0 = c * CHUNK;

#pragma unroll
    for (int p = 0; p < 4; p++) {
        const int idx = tid + p * 256;
        const int r = idx >> 4;
        const int c4 = (idx & 15) * 4;
        *(float4*)&Qs[r * PS + c4] =
            *(const float4*)&g_q[(size_t)(t0 + r) * HID + h * HD + c4];
        *(float4*)&Kb[r * PS + c4] =
            *(const float4*)&g_k[(size_t)(t0 + r) * HID + h * HD + c4];
        *(float4*)&Spt[r * PS + c4] =
            *(const float4*)&g_S[(size_t)(h * NCHUNK + c) * HD * HD + r * HD + c4];
        float4 vv = *(const float4*)&g_v[(size_t)(t0 + r) * HID + h * HD + c4];
        Vt[(c4 + 0) * PS + r] = vv.x; Vt[(c4 + 1) * PS + r] = vv.y;
        Vt[(c4 + 2) * PS + r] = vv.z; Vt[(c4 + 3) * PS + r] = vv.w;
    }
    if (tid < HD) zprev[tid] = g_Z[(size_t)(h * NCHUNK + c) * HD + tid];
    __syncthreads();

    const int w = tid >> 5, lane = tid & 31;
    const int g = lane >> 2, l4 = lane & 3;
    const int wm = (w >> 1) * 16;
    const int wn = (w & 1) * 32;
    const int t1 = wm + g, t2 = wm + g + 8;

    // ---- product 1: QK^T (3xTF32) ----
    float c1[4][4];
#pragma unroll
    for (int ni = 0; ni < 4; ni++)
#pragma unroll
        for (int q = 0; q < 4; q++) c1[ni][q] = 0.f;
#pragma unroll
    for (int ks = 0; ks < 8; ks++) {
        const int k0 = ks * 8;
        uint32_t ah[4], al[4];
        split32(Qs[t1 * PS + k0 + l4],     ah[0], al[0]);
        split32(Qs[t2 * PS + k0 + l4],     ah[1], al[1]);
        split32(Qs[t1 * PS + k0 + l4 + 4], ah[2], al[2]);
        split32(Qs[t2 * PS + k0 + l4 + 4], ah[3], al[3]);
#pragma unroll
        for (int ni = 0; ni < 4; ni++) {
            const int s = wn + ni * 8 + g;
            uint32_t bh[2], bl[2];
            split32(Kb[s * PS + k0 + l4],     bh[0], bl[0]);
            split32(Kb[s * PS + k0 + l4 + 4], bh[1], bl[1]);
            MMA3(c1[ni], ah, al, bh, bl);
        }
    }
    // mask + write Am + row sums
    float tot1 = 0.f, tot2 = 0.f;
#pragma unroll
    for (int ni = 0; ni < 4; ni++) {
        const int s0 = wn + ni * 8 + 2 * l4;
        float m00 = (s0     <= t1) ? c1[ni][0] : 0.f;
        float m01 = (s0 + 1 <= t1) ? c1[ni][1] : 0.f;
        float m10 = (s0     <= t2) ? c1[ni][2] : 0.f;
        float m11 = (s0 + 1 <= t2) ? c1[ni][3] : 0.f;
        tot1 += m00 + m01;
        tot2 += m10 + m11;
        *(float2*)&Am[t1 * PS + s0] = make_float2(m00, m01);
        *(float2*)&Am[t2 * PS + s0] = make_float2(m10, m11);
    }
#pragma unroll
    for (int j = 0; j < 8; j++) {
        const int d = wn + l4 * 8 + j;
        tot1 = fmaf(Qs[t1 * PS + d], zprev[d], tot1);
        tot2 = fmaf(Qs[t2 * PS + d], zprev[d], tot2);
    }
#pragma unroll
    for (int m = 1; m < 4; m <<= 1) {
        tot1 += __shfl_xor_sync(0xffffffffu, tot1, m);
        tot2 += __shfl_xor_sync(0xffffffffu, tot2, m);
    }
    if (l4 == 0) {
        rowpart[t1][w & 1] = tot1;
        rowpart[t2][w & 1] = tot2;
    }
    __syncthreads();
    if (tid < CHUNK) dinv[tid] = 1.f / fmaxf(rowpart[tid][0] + rowpart[tid][1], 1e-6f);

    // ---- products 2+3: O = Q@Spt^T + Am@V (3xTF32) ----
    float o[4][4];
#pragma unroll
    for (int ni = 0; ni < 4; ni++)
#pragma unroll
        for (int q = 0; q < 4; q++) o[ni][q] = 0.f;
#pragma unroll
    for (int ks = 0; ks < 8; ks++) {
        const int k0 = ks * 8;
        uint32_t ah[4], al[4];
        split32(Qs[t1 * PS + k0 + l4],     ah[0], al[0]);
        split32(Qs[t2 * PS + k0 + l4],     ah[1], al[1]);
        split32(Qs[t1 * PS + k0 + l4 + 4], ah[2], al[2]);
        split32(Qs[t2 * PS + k0 + l4 + 4], ah[3], al[3]);
#pragma unroll
        for (int ni = 0; ni < 4; ni++) {
            const int e = wn + ni * 8 + g;
            uint32_t bh[2], bl[2];
            split32(Spt[e * PS + k0 + l4],     bh[0], bl[0]);
            split32(Spt[e * PS + k0 + l4 + 4], bh[1], bl[1]);
            MMA3(o[ni], ah, al, bh, bl);
        }
    }
#pragma unroll
    for (int ks = 0; ks < 8; ks++) {
        const int k0 = ks * 8;
        uint32_t ah[4], al[4];
        split32(Am[t1 * PS + k0 + l4],     ah[0], al[0]);
        split32(Am[t2 * PS + k0 + l4],     ah[1], al[1]);
        split32(Am[t1 * PS + k0 + l4 + 4], ah[2], al[2]);
        split32(Am[t2 * PS + k0 + l4 + 4], ah[3], al[3]);
#pragma unroll
        for (int ni = 0; ni < 4; ni++) {
            const int e = wn + ni * 8 + g;
            uint32_t bh[2], bl[2];
            split32(Vt[e * PS + k0 + l4],     bh[0], bl[0]);
            split32(Vt[e * PS + k0 + l4 + 4], bh[1], bl[1]);
            MMA3(o[ni], ah, al, bh, bl);
        }
    }
    __syncthreads();

    const float d1 = dinv[t1];
    const float d2 = dinv[t2];
#pragma unroll
    for (int ni = 0; ni < 4; ni++) {
        const int e0 = wn + ni * 8 + 2 * l4;
        float2 r1 = make_float2(rndtf32(o[ni][0] * d1), rndtf32(o[ni][1] * d1));
        float2 r2 = make_float2(rndtf32(o[ni][2] * d2), rndtf32(o[ni][3] * d2));
        *(float2*)&g_att[(size_t)(t0 + t1) * HID + h * HD + e0] = r1;
        *(float2*)&g_att[(size_t)(t0 + t2) * HID + h * HD + e0] = r2;
    }
}

#define CO_SMEM (5 * 64 * PS * 4)

// ---------------- launch ----------------
extern "C" void kernel_launch(void* const* d_in, const int* in_sizes, int n_in,
                              void* d_out, int out_size)
{
    const float* x  = (const float*)d_in[0];
    const float* Wq = (const float*)d_in[1];
    const float* Wk = (const float*)d_in[2];
    const float* Wv = (const float*)d_in[3];
    const float* Wo = (const float*)d_in[4];
    float* out = (float*)d_out;

    static int attr_set = 0;
    if (!attr_set) {
        cudaFuncSetAttribute(chunk_out_kernel,
                             cudaFuncAttributeMaxDynamicSharedMemorySize, CO_SMEM);
        cudaFuncSetAttribute(chunk_stats_kernel,
                             cudaFuncAttributeMaxDynamicSharedMemorySize, STATS_SMEM);
        cudaFuncSetAttribute(gemm_qkv_kernel,
                             cudaFuncAttributeMaxDynamicSharedMemorySize, GEMM_SMEM);
        cudaFuncSetAttribute(gemm_out_kernel,
                             cudaFuncAttributeMaxDynamicSharedMemorySize, GEMM_SMEM);
        attr_set = 1;
    }

    const int TOT4 = X4 + 4 * W4;
    round_all_kernel<<<TOT4 / 256, 256>>>(x, Wq, Wk, Wv, Wo);

    dim3 gq(HID / 128, SEQ / 128, 3);
    gemm_qkv_kernel<<<gq, 256, GEMM_SMEM>>>();

    chunk_stats_kernel<<<dim3(NCHUNK, NH), 256, STATS_SMEM>>>();
    chunk_scan_kernel<<<SCAN_S_BLOCKS + NH * HD / 256, 256>>>();
    chunk_out_kernel<<<dim3(NCHUNK, NH), 256, CO_SMEM>>>();

    dim3 go(HID / 128, SEQ / 128);
    gemm_out_kernel<<<go, 256, GEMM_SMEM>>>(out);
}

// round 17
// speedup vs baseline: 1.0356x; 1.0356x over previous
#include <cuda_runtime.h>
#include <math.h>
#include <stdint.h>

#define SEQ 2048
#define HID 1024
#define NH 16
#define HD 64
#define CHUNK 64
#define NCHUNK (SEQ / CHUNK)

// ---------------- scratch ----------------
__device__ float g_q[SEQ * HID];
__device__ float g_k[SEQ * HID];
__device__ float g_v[SEQ * HID];
__device__ float g_att[SEQ * HID];            // pre-rounded to tf32
__device__ float g_S[NH * NCHUNK * HD * HD];  // stored TRANSPOSED: S_store[e][d] = S[d][e]
__device__ float g_Z[NH * NCHUNK * HD];
__device__ float g_xr[SEQ * HID];
__device__ float g_wqr[HID * HID];
__device__ float g_wkr[HID * HID];
__device__ float g_wvr[HID * HID];
__device__ float g_wor[HID * HID];

__device__ __forceinline__ uint32_t f2tf32(float f) {
    uint32_t u;
    asm("cvt.rna.tf32.f32 %0, %1;" : "=r"(u) : "f"(f));
    return u;
}
__device__ __forceinline__ float rndtf32(float f) { return __uint_as_float(f2tf32(f)); }
__device__ __forceinline__ uint32_t smem_u32(const void* p) {
    uint32_t a;
    asm("{ .reg .u64 t; cvta.to.shared.u64 t, %1; cvt.u32.u64 %0, t; }" : "=r"(a) : "l"(p));
    return a;
}
__device__ __forceinline__ void split32(float f, uint32_t& hi, uint32_t& lo) {
    float fh = rndtf32(f);
    hi = __float_as_uint(fh);
    lo = f2tf32(f - fh);
}

#define MMA_TF32(c0,c1,c2,c3,a0,a1,a2,a3,b0,b1) \
    asm volatile("mma.sync.aligned.m16n8k8.row.col.f32.tf32.tf32.f32 " \
                 "{%0,%1,%2,%3}, {%4,%5,%6,%7}, {%8,%9}, {%0,%1,%2,%3};" \
                 : "+f"(c0), "+f"(c1), "+f"(c2), "+f"(c3) \
                 : "r"(a0), "r"(a1), "r"(a2), "r"(a3), "r"(b0), "r"(b1))

#define MMA3(C, ah, al, bh, bl) do { \
    MMA_TF32(C[0],C[1],C[2],C[3], ah[0],ah[1],ah[2],ah[3], bh[0],bh[1]); \
    MMA_TF32(C[0],C[1],C[2],C[3], ah[0],ah[1],ah[2],ah[3], bl[0],bl[1]); \
    MMA_TF32(C[0],C[1],C[2],C[3], al[0],al[1],al[2],al[3], bh[0],bh[1]); \
} while (0)

// ---------------- fused pre-round pass ----------------
#define X4 (SEQ * HID / 4)
#define W4 (HID * HID / 4)
__global__ __launch_bounds__(256) void round_all_kernel(
    const float* __restrict__ x, const float* __restrict__ Wq,
    const float* __restrict__ Wk, const float* __restrict__ Wv,
    const float* __restrict__ Wo)
{
    int i = blockIdx.x * 256 + threadIdx.x;
    const float4* src;
    float4* dst;
    int off;
    if (i < X4) { src = (const float4*)x; dst = (float4*)g_xr; off = i; }
    else {
        int j = i - X4;
        int seg = j >> 18;
        off = j & (W4 - 1);
        src = (const float4*)((seg == 0) ? Wq : (seg == 1) ? Wk : (seg == 2) ? Wv : Wo);
        dst = (float4*)((seg == 0) ? g_wqr : (seg == 1) ? g_wkr : (seg == 2) ? g_wvr : g_wor);
    }
    float4 v = src[off];
    v.x = rndtf32(v.x); v.y = rndtf32(v.y); v.z = rndtf32(v.z); v.w = rndtf32(v.w);
    dst[off] = v;
}

// ================= pipelined tf32 mma GEMM (R11 schedule) =================
#define GBK 32
#define GSTRIDE 36
#define NSTAGE (HID / GBK)
#define NBUF 3
#define TILE_FLOATS (128 * GSTRIDE)
#define STAGE_FLOATS (2 * TILE_FLOATS)
#define GEMM_SMEM (NBUF * STAGE_FLOATS * 4)

__device__ __forceinline__ void cpasync16(uint32_t saddr, const float* gaddr) {
    asm volatile("cp.async.cg.shared.global [%0], [%1], 16;" :: "r"(saddr), "l"(gaddr));
}

__device__ __forceinline__ void gemm_body(const float* __restrict__ A,
                                          const float* __restrict__ B,
                                          float* __restrict__ C, int act,
                                          int m0, int n0, char* smem)
{
    const uint32_t sbase = smem_u32(smem);
    const int tid = threadIdx.x;
    const int w = tid >> 5;
    const int lane = tid & 31;
    const int g = lane >> 2;
    const int l4 = lane & 3;
    const int wm = (w >> 2) * 64;
    const int wn = (w & 3) * 32;

    float c[4][4][4];
#pragma unroll
    for (int mi = 0; mi < 4; mi++)
#pragma unroll
        for (int ni = 0; ni < 4; ni++)
#pragma unroll
            for (int q = 0; q < 4; q++) c[mi][ni][q] = 0.f;

    auto prefetch = [&](int s) {
        const int b = s % NBUF;
        const uint32_t ab = sbase + (uint32_t)(b * STAGE_FLOATS) * 4;
        const uint32_t bb = ab + TILE_FLOATS * 4;
        const int k0 = s * GBK;
#pragma unroll
        for (int p = 0; p < 4; p++) {
            const int idx = tid + p * 256;
            const int r = idx >> 3, kk = (idx & 7) * 4;
            cpasync16(ab + (r * GSTRIDE + kk) * 4, &A[(size_t)(m0 + r) * HID + k0 + kk]);
            cpasync16(bb + (r * GSTRIDE + kk) * 4, &B[(size_t)(n0 + r) * HID + k0 + kk]);
        }
        asm volatile("cp.async.commit_group;" ::: "memory");
    };

    prefetch(0);
    prefetch(1);

    for (int s = 0; s < NSTAGE; s++) {
        asm volatile("cp.async.wait_group 1;" ::: "memory");
        __syncthreads();
        if (s + 2 < NSTAGE) prefetch(s + 2);

        const int b = s % NBUF;
        const float* As = (const float*)(smem) + b * STAGE_FLOATS;
        const float* Bs = As + TILE_FLOATS;

#pragma unroll
        for (int kk = 0; kk < GBK; kk += 8) {
            uint32_t a[4][4], bq[4][2];
#pragma unroll
            for (int mi = 0; mi < 4; mi++) {
                const int r = wm + mi * 16 + g;
                a[mi][0] = __float_as_uint(As[r * GSTRIDE + kk + l4]);
                a[mi][1] = __float_as_uint(As[(r + 8) * GSTRIDE + kk + l4]);
                a[mi][2] = __float_as_uint(As[r * GSTRIDE + kk + l4 + 4]);
                a[mi][3] = __float_as_uint(As[(r + 8) * GSTRIDE + kk + l4 + 4]);
            }
#pragma unroll
            for (int ni = 0; ni < 4; ni++) {
                const int r = wn + ni * 8 + g;
                bq[ni][0] = __float_as_uint(Bs[r * GSTRIDE + kk + l4]);
                bq[ni][1] = __float_as_uint(Bs[r * GSTRIDE + kk + l4 + 4]);
            }
#pragma unroll
            for (int mi = 0; mi < 4; mi++)
#pragma unroll
                for (int ni = 0; ni < 4; ni++)
                    MMA_TF32(c[mi][ni][0], c[mi][ni][1], c[mi][ni][2], c[mi][ni][3],
                             a[mi][0], a[mi][1], a[mi][2], a[mi][3],
                             bq[ni][0], bq[ni][1]);
        }
        __syncthreads();
    }
    asm volatile("cp.async.wait_group 0;" ::: "memory");

#pragma unroll
    for (int mi = 0; mi < 4; mi++) {
#pragma unroll
        for (int ri = 0; ri < 2; ri++) {
            const int m = m0 + wm + mi * 16 + g + ri * 8;
#pragma unroll
            for (int ni = 0; ni < 4; ni++) {
                float y0 = c[mi][ni][ri * 2 + 0];
                float y1 = c[mi][ni][ri * 2 + 1];
                if (act) {
                    y0 = (y0 > 0.f) ? (y0 + 1.f) : expf(y0);
                    y1 = (y1 > 0.f) ? (y1 + 1.f) : expf(y1);
                }
                const int n = n0 + wn + ni * 8 + l4 * 2;
                *(float2*)&C[(size_t)m * HID + n] = make_float2(y0, y1);
            }
        }
    }
}

extern __shared__ char sm_g[];
__global__ __launch_bounds__(256, 2) void gemm_qkv_kernel()
{
    const int z = blockIdx.z;
    const float* W = (z == 0) ? g_wqr : (z == 1) ? g_wkr : g_wvr;
    float* dst = (z == 0) ? g_q : (z == 1) ? g_k : g_v;
    gemm_body(g_xr, W, dst, z != 2, blockIdx.y * 128, blockIdx.x * 128, sm_g);
}
__global__ __launch_bounds__(256, 2) void gemm_out_kernel(float* __restrict__ out)
{
    gemm_body(g_att, g_wor, out, 0, blockIdx.y * 128, blockIdx.x * 128, sm_g);
}

// ================= Pass A: per-chunk S=K^T V (3xTF32, R11 version) =================
#define PS 68
__global__ __launch_bounds__(256) void chunk_stats_kernel()
{
    const int c = blockIdx.x;
    const int h = blockIdx.y;
    __shared__ float Kt[64 * PS];   // Kt[d][t]
    __shared__ float Vt[64 * PS];   // Vt[e][t]

    const int tid = threadIdx.x;
    const int t0 = c * CHUNK;

#pragma unroll
    for (int p = 0; p < 4; p++) {
        const int idx = tid + p * 256;
        const int t = idx >> 4;
        const int e4 = (idx & 15) * 4;
        float4 kv = *(const float4*)&g_k[(size_t)(t0 + t) * HID + h * HD + e4];
        Kt[(e4 + 0) * PS + t] = kv.x; Kt[(e4 + 1) * PS + t] = kv.y;
        Kt[(e4 + 2) * PS + t] = kv.z; Kt[(e4 + 3) * PS + t] = kv.w;
        float4 vv = *(const float4*)&g_v[(size_t)(t0 + t) * HID + h * HD + e4];
        Vt[(e4 + 0) * PS + t] = vv.x; Vt[(e4 + 1) * PS + t] = vv.y;
        Vt[(e4 + 2) * PS + t] = vv.z; Vt[(e4 + 3) * PS + t] = vv.w;
    }
    __syncthreads();

    if (tid < HD) {
        float z = 0.f;
        for (int t = 0; t < CHUNK; t++) z += Kt[tid * PS + t];
        g_Z[(size_t)(h * NCHUNK + c) * HD + tid] = z;
    }

    const int w = tid >> 5, lane = tid & 31;
    const int g = lane >> 2, l4 = lane & 3;
    const int wm = (w >> 1) * 16;
    const int wn = (w & 1) * 32;

    float cc[4][4];
#pragma unroll
    for (int ni = 0; ni < 4; ni++)
#pragma unroll
        for (int q = 0; q < 4; q++) cc[ni][q] = 0.f;

#pragma unroll
    for (int ks = 0; ks < 8; ks++) {
        const int k0 = ks * 8;
        uint32_t ah[4], al[4];
        split32(Vt[(wm + g) * PS + k0 + l4],         ah[0], al[0]);
        split32(Vt[(wm + g + 8) * PS + k0 + l4],     ah[1], al[1]);
        split32(Vt[(wm + g) * PS + k0 + l4 + 4],     ah[2], al[2]);
        split32(Vt[(wm + g + 8) * PS + k0 + l4 + 4], ah[3], al[3]);
#pragma unroll
        for (int ni = 0; ni < 4; ni++) {
            const int d = wn + ni * 8 + g;
            uint32_t bh[2], bl[2];
            split32(Kt[d * PS + k0 + l4],     bh[0], bl[0]);
            split32(Kt[d * PS + k0 + l4 + 4], bh[1], bl[1]);
            MMA3(cc[ni], ah, al, bh, bl);
        }
    }

    float* Sout = g_S + (size_t)(h * NCHUNK + c) * HD * HD;
#pragma unroll
    for (int ni = 0; ni < 4; ni++) {
        const int d = wn + ni * 8 + l4 * 2;
        *(float2*)&Sout[(wm + g) * HD + d]     = make_float2(cc[ni][0], cc[ni][1]);
        *(float2*)&Sout[(wm + g + 8) * HD + d] = make_float2(cc[ni][2], cc[ni][3]);
    }
}

// ---------------- Pass B: PARALLEL exclusive scan, register-batched (MLP=16) ----------------
#define SCAN_S_BLOCKS (NH * HD * HD / 256)   // 256
__global__ __launch_bounds__(256) void chunk_scan_kernel()
{
    const int bid = blockIdx.x;
    const int tid = threadIdx.x;
    if (bid < SCAN_S_BLOCKS) {
        const int gidx = bid * 256 + tid;
        const int h = gidx >> 12;
        const int e = gidx & 4095;
        float* p = g_S + (size_t)h * NCHUNK * HD * HD + e;
        float acc = 0.f;
#pragma unroll
        for (int b = 0; b < 2; b++) {
            float v[16];
#pragma unroll
            for (int i = 0; i < 16; i++)
                v[i] = p[(size_t)(b * 16 + i) * (HD * HD)];
#pragma unroll
            for (int i = 0; i < 16; i++) {
                p[(size_t)(b * 16 + i) * (HD * HD)] = acc;
                acc += v[i];
            }
        }
    } else {
        const int j = (bid - SCAN_S_BLOCKS) * 256 + tid;
        const int h = j >> 6;
        const int d = j & 63;
        float* p = g_Z + (size_t)h * NCHUNK * HD + d;
        float acc = 0.f;
#pragma unroll
        for (int b = 0; b < 2; b++) {
            float v[16];
#pragma unroll
            for (int i = 0; i < 16; i++)
                v[i] = p[(b * 16 + i) * HD];
#pragma unroll
            for (int i = 0; i < 16; i++) {
                p[(b * 16 + i) * HD] = acc;
                acc += v[i];
            }
        }
    }
}

// ================= Pass C: per-chunk output (3xTF32, fused Q-split sharing) =================
extern __shared__ float sm_c[];
__global__ __launch_bounds__(256) void chunk_out_kernel()
{
    const int c = blockIdx.x;
    const int h = blockIdx.y;
    float* Qs  = sm_c;                 // [64][PS] (t,d)
    float* Kb  = Qs + 64 * PS;         // [64][PS] (s,d)
    float* Spt = Kb + 64 * PS;         // [64][PS] S_store[e][d]
    float* Vt  = Spt + 64 * PS;        // [64][PS] Vt[e][s]
    float* Am  = Vt + 64 * PS;         // [64][PS] masked QK^T (t,s)
    __shared__ float zprev[HD];
    __shared__ float rowpart[HD][2];
    __shared__ float dinv[CHUNK];

    const int tid = threadIdx.x;
    const int t0 = c * CHUNK;

#pragma unroll
    for (int p = 0; p < 4; p++) {
        const int idx = tid + p * 256;
        const int r = idx >> 4;
        const int c4 = (idx & 15) * 4;
        *(float4*)&Qs[r * PS + c4] =
            *(const float4*)&g_q[(size_t)(t0 + r) * HID + h * HD + c4];
        *(float4*)&Kb[r * PS + c4] =
            *(const float4*)&g_k[(size_t)(t0 + r) * HID + h * HD + c4];
        *(float4*)&Spt[r * PS + c4] =
            *(const float4*)&g_S[(size_t)(h * NCHUNK + c) * HD * HD + r * HD + c4];
        float4 vv = *(const float4*)&g_v[(size_t)(t0 + r) * HID + h * HD + c4];
        Vt[(c4 + 0) * PS + r] = vv.x; Vt[(c4 + 1) * PS + r] = vv.y;
        Vt[(c4 + 2) * PS + r] = vv.z; Vt[(c4 + 3) * PS + r] = vv.w;
    }
    if (tid < HD) zprev[tid] = g_Z[(size_t)(h * NCHUNK + c) * HD + tid];
    __syncthreads();

    const int w = tid >> 5, lane = tid & 31;
    const int g = lane >> 2, l4 = lane & 3;
    const int wm = (w >> 1) * 16;
    const int wn = (w & 1) * 32;
    const int t1 = wm + g, t2 = wm + g + 8;

    // ---- FUSED products 1 (QK^T -> c1) and 2 (Q@Spt^T -> o): share Q splits ----
    float c1[4][4], o[4][4];
#pragma unroll
    for (int ni = 0; ni < 4; ni++)
#pragma unroll
        for (int q = 0; q < 4; q++) { c1[ni][q] = 0.f; o[ni][q] = 0.f; }
#pragma unroll
    for (int ks = 0; ks < 8; ks++) {
        const int k0 = ks * 8;
        uint32_t ah[4], al[4];
        split32(Qs[t1 * PS + k0 + l4],     ah[0], al[0]);
        split32(Qs[t2 * PS + k0 + l4],     ah[1], al[1]);
        split32(Qs[t1 * PS + k0 + l4 + 4], ah[2], al[2]);
        split32(Qs[t2 * PS + k0 + l4 + 4], ah[3], al[3]);
#pragma unroll
        for (int ni = 0; ni < 4; ni++) {
            const int s = wn + ni * 8 + g;
            uint32_t bh[2], bl[2];
            split32(Kb[s * PS + k0 + l4],     bh[0], bl[0]);
            split32(Kb[s * PS + k0 + l4 + 4], bh[1], bl[1]);
            MMA3(c1[ni], ah, al, bh, bl);
        }
#pragma unroll
        for (int ni = 0; ni < 4; ni++) {
            const int e = wn + ni * 8 + g;
            uint32_t bh[2], bl[2];
            split32(Spt[e * PS + k0 + l4],     bh[0], bl[0]);
            split32(Spt[e * PS + k0 + l4 + 4], bh[1], bl[1]);
            MMA3(o[ni], ah, al, bh, bl);
        }
    }
    // mask + write Am + row sums
    float tot1 = 0.f, tot2 = 0.f;
#pragma unroll
    for (int ni = 0; ni < 4; ni++) {
        const int s0 = wn + ni * 8 + 2 * l4;
        float m00 = (s0     <= t1) ? c1[ni][0] : 0.f;
        float m01 = (s0 + 1 <= t1) ? c1[ni][1] : 0.f;
        float m10 = (s0     <= t2) ? c1[ni][2] : 0.f;
        float m11 = (s0 + 1 <= t2) ? c1[ni][3] : 0.f;
        tot1 += m00 + m01;
        tot2 += m10 + m11;
        *(float2*)&Am[t1 * PS + s0] = make_float2(m00, m01);
        *(float2*)&Am[t2 * PS + s0] = make_float2(m10, m11);
    }
#pragma unroll
    for (int j = 0; j < 8; j++) {
        const int d = wn + l4 * 8 + j;
        tot1 = fmaf(Qs[t1 * PS + d], zprev[d], tot1);
        tot2 = fmaf(Qs[t2 * PS + d], zprev[d], tot2);
    }
#pragma unroll
    for (int m = 1; m < 4; m <<= 1) {
        tot1 += __shfl_xor_sync(0xffffffffu, tot1, m);
        tot2 += __shfl_xor_sync(0xffffffffu, tot2, m);
    }
    if (l4 == 0) {
        rowpart[t1][w & 1] = tot1;
        rowpart[t2][w & 1] = tot2;
    }
    __syncthreads();
    if (tid < CHUNK) dinv[tid] = 1.f / fmaxf(rowpart[tid][0] + rowpart[tid][1], 1e-6f);

    // ---- product 3: O += Am@V (3xTF32) ----
#pragma unroll
    for (int ks = 0; ks < 8; ks++) {
        const int k0 = ks * 8;
        uint32_t ah[4], al[4];
        split32(Am[t1 * PS + k0 + l4],     ah[0], al[0]);
        split32(Am[t2 * PS + k0 + l4],     ah[1], al[1]);
        split32(Am[t1 * PS + k0 + l4 + 4], ah[2], al[2]);
        split32(Am[t2 * PS + k0 + l4 + 4], ah[3], al[3]);
#pragma unroll
        for (int ni = 0; ni < 4; ni++) {
            const int e = wn + ni * 8 + g;
            uint32_t bh[2], bl[2];
            split32(Vt[e * PS + k0 + l4],     bh[0], bl[0]);
            split32(Vt[e * PS + k0 + l4 + 4], bh[1], bl[1]);
            MMA3(o[ni], ah, al, bh, bl);
        }
    }
    __syncthreads();

    const float d1 = dinv[t1];
    const float d2 = dinv[t2];
#pragma unroll
    for (int ni = 0; ni < 4; ni++) {
        const int e0 = wn + ni * 8 + 2 * l4;
        float2 r1 = make_float2(rndtf32(o[ni][0] * d1), rndtf32(o[ni][1] * d1));
        float2 r2 = make_float2(rndtf32(o[ni][2] * d2), rndtf32(o[ni][3] * d2));
        *(float2*)&g_att[(size_t)(t0 + t1) * HID + h * HD + e0] = r1;
        *(float2*)&g_att[(size_t)(t0 + t2) * HID + h * HD + e0] = r2;
    }
}

#define CO_SMEM (5 * 64 * PS * 4)

// ---------------- launch ----------------
extern "C" void kernel_launch(void* const* d_in, const int* in_sizes, int n_in,
                              void* d_out, int out_size)
{
    const float* x  = (const float*)d_in[0];
    const float* Wq = (const float*)d_in[1];
    const float* Wk = (const float*)d_in[2];
    const float* Wv = (const float*)d_in[3];
    const float* Wo = (const float*)d_in[4];
    float* out = (float*)d_out;

    static int attr_set = 0;
    if (!attr_set) {
        cudaFuncSetAttribute(chunk_out_kernel,
                             cudaFuncAttributeMaxDynamicSharedMemorySize, CO_SMEM);
        cudaFuncSetAttribute(gemm_qkv_kernel,
                             cudaFuncAttributeMaxDynamicSharedMemorySize, GEMM_SMEM);
        cudaFuncSetAttribute(gemm_out_kernel,
                             cudaFuncAttributeMaxDynamicSharedMemorySize, GEMM_SMEM);
        attr_set = 1;
    }

    const int TOT4 = X4 + 4 * W4;
    round_all_kernel<<<TOT4 / 256, 256>>>(x, Wq, Wk, Wv, Wo);

    dim3 gq(HID / 128, SEQ / 128, 3);
    gemm_qkv_kernel<<<gq, 256, GEMM_SMEM>>>();

    chunk_stats_kernel<<<dim3(NCHUNK, NH), 256>>>();
    chunk_scan_kernel<<<SCAN_S_BLOCKS + NH * HD / 256, 256>>>();
    chunk_out_kernel<<<dim3(NCHUNK, NH), 256, CO_SMEM>>>();

    dim3 go(HID / 128, SEQ / 128);
    gemm_out_kernel<<<go, 256, GEMM_SMEM>>>(out);
}